// round 1
// baseline (speedup 1.0000x reference)
#include <cuda_runtime.h>
#include <cstdint>
#include <cstddef>

// Problem constants
#define BATCH   16384
#define DIM     512
#define HID     128     // H
#define HID2    256     // 2H
#define NG      18
#define DAGG    640     // D + H

// ---------------------------------------------------------------------------
// Scratch (device globals; allocation-free rule)
// ---------------------------------------------------------------------------
__device__ float g_w[(size_t)BATCH * NG];                    // masked attention weights
__device__ float g_buf1[(size_t)NG * BATCH * HID2];          // H1, later reused for H3
__device__ float g_H2[(size_t)NG * BATCH * HID];             // H2
__device__ float g_R[(size_t)BATCH * HID];                   // refinements

// ---------------------------------------------------------------------------
// tf32 helpers
// ---------------------------------------------------------------------------
__device__ __forceinline__ uint32_t f2tf(float f) {
    uint32_t u;
    asm("cvt.rna.tf32.f32 %0, %1;" : "=r"(u) : "f"(f));
    return u;
}

__device__ __forceinline__ void mma8(float* d, const uint32_t* a, const uint32_t* b) {
    asm volatile(
        "mma.sync.aligned.m16n8k8.row.col.f32.tf32.tf32.f32 "
        "{%0,%1,%2,%3}, {%4,%5,%6,%7}, {%8,%9}, {%0,%1,%2,%3};"
        : "+f"(d[0]), "+f"(d[1]), "+f"(d[2]), "+f"(d[3])
        : "r"(a[0]), "r"(a[1]), "r"(a[2]), "r"(a[3]), "r"(b[0]), "r"(b[1]));
}

// ---------------------------------------------------------------------------
// Attention kernel: logits = X @ Wa + ba, softmax over G, mask by membership
// One warp per row; Wa cached in smem with pad-19 stride (conflict-free).
// ---------------------------------------------------------------------------
__global__ __launch_bounds__(256)
void attn_kernel(const float* __restrict__ X, const float* __restrict__ genre,
                 const float* __restrict__ Wa, const float* __restrict__ ba,
                 float* __restrict__ w) {
    __shared__ float Was[DIM * 19];
    __shared__ float bas[32];
    int tid = threadIdx.x;
    for (int i = tid; i < DIM * NG; i += 256) {
        int d = i / NG, g = i % NG;
        Was[d * 19 + g] = Wa[i];
    }
    if (tid < NG) bas[tid] = ba[tid];
    __syncthreads();

    int warp = tid >> 5, lane = tid & 31;
    for (int it = 0; it < 8; ++it) {
        int b = blockIdx.x * 64 + it * 8 + warp;
        // per-lane partial dot products over this lane's slice of x
        float acc[NG];
        #pragma unroll
        for (int g = 0; g < NG; g++) acc[g] = 0.f;
        #pragma unroll
        for (int i = 0; i < 16; i++) {
            int d = 32 * i + lane;
            float xv = X[(size_t)b * DIM + d];
            const float* wrow = &Was[d * 19];
            #pragma unroll
            for (int g = 0; g < NG; g++) acc[g] += xv * wrow[g];
        }
        // butterfly reduce each genre across lanes
        #pragma unroll
        for (int off = 16; off > 0; off >>= 1) {
            #pragma unroll
            for (int g = 0; g < NG; g++)
                acc[g] += __shfl_xor_sync(0xffffffffu, acc[g], off);
        }
        #pragma unroll
        for (int g = 0; g < NG; g++) acc[g] += bas[g];
        // softmax (every lane redundantly)
        float mx = acc[0];
        #pragma unroll
        for (int g = 1; g < NG; g++) mx = fmaxf(mx, acc[g]);
        float s = 0.f, e_own = 0.f;
        #pragma unroll
        for (int g = 0; g < NG; g++) {
            float e = expf(acc[g] - mx);
            s += e;
            if (g == lane) e_own = e;
        }
        if (lane < NG) {
            float attn = e_own / s;
            float gv = genre[(size_t)b * NG + lane];
            w[(size_t)b * NG + lane] = (gv > 0.f) ? attn * gv : 0.f;
        }
    }
}

// ---------------------------------------------------------------------------
// tf32 GEMM template: C = act(A[M,K] @ W[K,N] + bias[N])
// Block tile 128x128, K-chunk 32, 8 warps (4x2), warp tile 32x64.
// blockIdx.z = genre; per-genre strides passed in.
// CONCAT mode: A is [X | R] along K (X: lda 512, R: lda 128).
// ---------------------------------------------------------------------------
#define BM 128
#define BN 128
#define BK 32
#define LDAS 36
#define LDBS 136

template<int ACT, bool CONCAT>
__global__ __launch_bounds__(256, 2)
void gemm_tf32_kernel(const float* __restrict__ A, const float* __restrict__ R,
                      const float* __restrict__ W, const float* __restrict__ bias,
                      float* __restrict__ C,
                      int M, int N, int K, int lda,
                      long long sA, long long sW, long long sB, long long sC) {
    int g = blockIdx.z;
    A    += (size_t)g * sA;
    W    += (size_t)g * sW;
    bias += (size_t)g * sB;
    C    += (size_t)g * sC;

    __shared__ float As[BM * LDAS];
    __shared__ float Ws[BK * LDBS];

    int tid  = threadIdx.x;
    int m0   = blockIdx.x * BM;
    int n0   = blockIdx.y * BN;
    int lane = tid & 31, warp = tid >> 5;
    int wm_base = (warp >> 1) * 32;
    int wn_base = (warp & 1) * 64;

    float acc[2][8][4];
    #pragma unroll
    for (int i = 0; i < 2; i++)
        #pragma unroll
        for (int j = 0; j < 8; j++)
            #pragma unroll
            for (int r = 0; r < 4; r++) acc[i][j][r] = 0.f;

    int ar = tid >> 3, ac = (tid & 7) * 4;     // A loader: 32 rows x 8 float4
    int wr = tid >> 5, wc = (tid & 31) * 4;    // W loader: 8 rows x 32 float4

    for (int k0 = 0; k0 < K; k0 += BK) {
        // ---- stage A tile [BM x BK] ----
        #pragma unroll
        for (int rr = 0; rr < 4; rr++) {
            int r = ar + rr * 32;
            int grow = m0 + r;
            int gcol = k0 + ac;
            float4 v;
            if (!CONCAT) {
                v = *(const float4*)(A + (size_t)grow * lda + gcol);
            } else {
                if (gcol < DIM)
                    v = *(const float4*)(A + (size_t)grow * DIM + gcol);
                else
                    v = *(const float4*)(R + (size_t)grow * HID + (gcol - DIM));
            }
            *(float4*)(As + r * LDAS + ac) = v;
        }
        // ---- stage W tile [BK x BN] ----
        #pragma unroll
        for (int rr = 0; rr < 4; rr++) {
            int r = wr + rr * 8;
            float4 v = *(const float4*)(W + (size_t)(k0 + r) * N + n0 + wc);
            *(float4*)(Ws + r * LDBS + wc) = v;
        }
        __syncthreads();

        #pragma unroll
        for (int kk = 0; kk < 4; kk++) {
            int kb = kk * 8;
            uint32_t afr[2][4], bfr[8][2];
            #pragma unroll
            for (int wm = 0; wm < 2; wm++) {
                int r = wm_base + wm * 16 + (lane >> 2);
                int c = kb + (lane & 3);
                afr[wm][0] = f2tf(As[r * LDAS + c]);
                afr[wm][1] = f2tf(As[(r + 8) * LDAS + c]);
                afr[wm][2] = f2tf(As[r * LDAS + c + 4]);
                afr[wm][3] = f2tf(As[(r + 8) * LDAS + c + 4]);
            }
            #pragma unroll
            for (int wn = 0; wn < 8; wn++) {
                int ccol = wn_base + wn * 8 + (lane >> 2);
                int rrow = kb + (lane & 3);
                bfr[wn][0] = f2tf(Ws[rrow * LDBS + ccol]);
                bfr[wn][1] = f2tf(Ws[(rrow + 4) * LDBS + ccol]);
            }
            #pragma unroll
            for (int wm = 0; wm < 2; wm++)
                #pragma unroll
                for (int wn = 0; wn < 8; wn++)
                    mma8(acc[wm][wn], afr[wm], bfr[wn]);
        }
        __syncthreads();
    }

    // ---- epilogue: + bias, optional relu, write ----
    #pragma unroll
    for (int wm = 0; wm < 2; wm++) {
        int r0 = m0 + wm_base + wm * 16 + (lane >> 2);
        #pragma unroll
        for (int wn = 0; wn < 8; wn++) {
            int c0 = n0 + wn_base + wn * 8 + 2 * (lane & 3);
            float b0 = bias[c0], b1v = bias[c0 + 1];
            float v0 = acc[wm][wn][0] + b0;
            float v1 = acc[wm][wn][1] + b1v;
            float v2 = acc[wm][wn][2] + b0;
            float v3 = acc[wm][wn][3] + b1v;
            if (ACT) {
                v0 = fmaxf(v0, 0.f); v1 = fmaxf(v1, 0.f);
                v2 = fmaxf(v2, 0.f); v3 = fmaxf(v3, 0.f);
            }
            float2 p0 = make_float2(v0, v1);
            float2 p1 = make_float2(v2, v3);
            *(float2*)(C + (size_t)r0 * N + c0)       = p0;
            *(float2*)(C + (size_t)(r0 + 8) * N + c0) = p1;
        }
    }
}

// ---------------------------------------------------------------------------
// Weighted reduce: R[b,:] = sum_g w[b,g] * H3[g,b,:]   (skip w==0, uniform warp)
// ---------------------------------------------------------------------------
__global__ __launch_bounds__(256)
void reduce_kernel(const float* __restrict__ H3, const float* __restrict__ w,
                   float* __restrict__ R) {
    int idx = blockIdx.x * blockDim.x + threadIdx.x;   // over BATCH * 32 float4s
    int b = idx >> 5;
    float4 r = make_float4(0.f, 0.f, 0.f, 0.f);
    const float4* H = (const float4*)H3;
    #pragma unroll
    for (int g = 0; g < NG; g++) {
        float wv = w[(size_t)b * NG + g];
        if (wv != 0.f) {
            float4 h = H[(size_t)g * (BATCH * 32) + idx];
            r.x += wv * h.x; r.y += wv * h.y;
            r.z += wv * h.z; r.w += wv * h.w;
        }
    }
    ((float4*)R)[idx] = r;
}

// ---------------------------------------------------------------------------
// Launch
// ---------------------------------------------------------------------------
extern "C" void kernel_launch(void* const* d_in, const int* in_sizes, int n_in,
                              void* d_out, int out_size) {
    (void)in_sizes; (void)n_in; (void)out_size;
    const float* X     = (const float*)d_in[0];
    const float* genre = (const float*)d_in[1];
    const float* W1    = (const float*)d_in[2];
    const float* b1    = (const float*)d_in[3];
    const float* W2    = (const float*)d_in[4];
    const float* b2    = (const float*)d_in[5];
    const float* W3    = (const float*)d_in[6];
    const float* b3    = (const float*)d_in[7];
    const float* Wa    = (const float*)d_in[8];
    const float* ba    = (const float*)d_in[9];
    const float* Wagg  = (const float*)d_in[10];
    const float* bagg  = (const float*)d_in[11];
    float* out = (float*)d_out;

    float *w, *buf1, *H2, *R;
    cudaGetSymbolAddress((void**)&w,    g_w);
    cudaGetSymbolAddress((void**)&buf1, g_buf1);
    cudaGetSymbolAddress((void**)&H2,   g_H2);
    cudaGetSymbolAddress((void**)&R,    g_R);

    // 1) attention weights (masked)
    attn_kernel<<<BATCH / 64, 256>>>(X, genre, Wa, ba, w);

    // 2) H1 = relu(X @ W1[g] + b1[g])  [per g]
    gemm_tf32_kernel<1, false><<<dim3(BATCH / BM, HID2 / BN, NG), 256>>>(
        X, nullptr, W1, b1, buf1,
        BATCH, HID2, DIM, DIM,
        0LL, (long long)DIM * HID2, HID2, (long long)BATCH * HID2);

    // 3) H2 = relu(H1 @ W2[g] + b2[g])
    gemm_tf32_kernel<1, false><<<dim3(BATCH / BM, 1, NG), 256>>>(
        buf1, nullptr, W2, b2, H2,
        BATCH, HID, HID2, HID2,
        (long long)BATCH * HID2, (long long)HID2 * HID, HID, (long long)BATCH * HID);

    // 4) H3 = H2 @ W3[g] + b3[g]   (reuse buf1; H1 is dead)
    gemm_tf32_kernel<0, false><<<dim3(BATCH / BM, 1, NG), 256>>>(
        H2, nullptr, W3, b3, buf1,
        BATCH, HID, HID, HID,
        (long long)BATCH * HID, (long long)HID * HID, HID, (long long)BATCH * HID);

    // 5) R = sum_g w .* H3
    reduce_kernel<<<(BATCH * 32) / 256, 256>>>(buf1, w, R);

    // 6) out = relu([X, R] @ Wagg + bagg)
    gemm_tf32_kernel<1, true><<<dim3(BATCH / BM, DIM / BN, 1), 256>>>(
        X, R, Wagg, bagg, out,
        BATCH, DIM, DAGG, DAGG,
        0LL, 0LL, 0LL, 0LL);
}

// round 3
// speedup vs baseline: 1.2086x; 1.2086x over previous
#include <cuda_runtime.h>
#include <cstdint>
#include <cstddef>

// Problem constants
#define BATCH   16384
#define DIM     512
#define HID     128     // H
#define HID2    256     // 2H
#define NG      18
#define DAGG    640     // D + H

// ---------------------------------------------------------------------------
// Scratch (device globals; allocation-free rule)
// ---------------------------------------------------------------------------
__device__ float g_w[(size_t)BATCH * NG];                    // masked attention weights
__device__ float g_buf1[(size_t)NG * BATCH * HID2];          // H1, later reused for H3
__device__ float g_H2[(size_t)NG * BATCH * HID];             // H2
__device__ float g_R[(size_t)BATCH * HID];                   // refinements
__device__ float g_Xr[(size_t)BATCH * DIM];                  // X rounded to tf32
__device__ float g_W1r[(size_t)NG * DIM * HID2];             // rounded weights
__device__ float g_W2r[(size_t)NG * HID2 * HID];
__device__ float g_W3r[(size_t)NG * HID * HID];
__device__ float g_Waggr[(size_t)DAGG * DIM];

// ---------------------------------------------------------------------------
// Helpers
// ---------------------------------------------------------------------------
__device__ __forceinline__ uint32_t f2tf(float f) {
    uint32_t u;
    asm("cvt.rna.tf32.f32 %0, %1;" : "=r"(u) : "f"(f));
    return u;
}
__device__ __forceinline__ float round_tf32(float f) {
    return __uint_as_float(f2tf(f));
}
__device__ __forceinline__ uint32_t smem_u32(const void* p) {
    uint32_t a;
    asm("{ .reg .u64 t; cvta.to.shared.u64 t, %1; cvt.u32.u64 %0, t; }" : "=r"(a) : "l"(p));
    return a;
}
__device__ __forceinline__ void cp_async16(uint32_t dst, const void* src) {
    asm volatile("cp.async.cg.shared.global [%0], [%1], 16;" :: "r"(dst), "l"(src) : "memory");
}
#define CP_COMMIT() asm volatile("cp.async.commit_group;" ::: "memory")
#define CP_WAIT(n)  asm volatile("cp.async.wait_group %0;" :: "n"(n) : "memory")

__device__ __forceinline__ void mma8(float* d, const uint32_t* a, const uint32_t* b) {
    asm volatile(
        "mma.sync.aligned.m16n8k8.row.col.f32.tf32.tf32.f32 "
        "{%0,%1,%2,%3}, {%4,%5,%6,%7}, {%8,%9}, {%0,%1,%2,%3};"
        : "+f"(d[0]), "+f"(d[1]), "+f"(d[2]), "+f"(d[3])
        : "r"(a[0]), "r"(a[1]), "r"(a[2]), "r"(a[3]), "r"(b[0]), "r"(b[1]));
}

// ---------------------------------------------------------------------------
// Generic tf32 rounding prep kernel (grid-stride over float4)
// ---------------------------------------------------------------------------
__global__ __launch_bounds__(256)
void round_kernel(const float* __restrict__ in, float* __restrict__ out, int n4) {
    int i = blockIdx.x * 256 + threadIdx.x;
    int stride = gridDim.x * 256;
    for (; i < n4; i += stride) {
        float4 v = ((const float4*)in)[i];
        v.x = round_tf32(v.x); v.y = round_tf32(v.y);
        v.z = round_tf32(v.z); v.w = round_tf32(v.w);
        ((float4*)out)[i] = v;
    }
}

// ---------------------------------------------------------------------------
// Attention kernel: logits = X @ Wa + ba, softmax over G, mask by membership
// ---------------------------------------------------------------------------
__global__ __launch_bounds__(256)
void attn_kernel(const float* __restrict__ X, const float* __restrict__ genre,
                 const float* __restrict__ Wa, const float* __restrict__ ba,
                 float* __restrict__ w) {
    __shared__ float Was[DIM * 19];
    __shared__ float bas[32];
    int tid = threadIdx.x;
    for (int i = tid; i < DIM * NG; i += 256) {
        int d = i / NG, g = i % NG;
        Was[d * 19 + g] = Wa[i];
    }
    if (tid < NG) bas[tid] = ba[tid];
    __syncthreads();

    int warp = tid >> 5, lane = tid & 31;
    for (int it = 0; it < 8; ++it) {
        int b = blockIdx.x * 64 + it * 8 + warp;
        float acc[NG];
        #pragma unroll
        for (int g = 0; g < NG; g++) acc[g] = 0.f;
        #pragma unroll
        for (int i = 0; i < 16; i++) {
            int d = 32 * i + lane;
            float xv = X[(size_t)b * DIM + d];
            const float* wrow = &Was[d * 19];
            #pragma unroll
            for (int g = 0; g < NG; g++) acc[g] += xv * wrow[g];
        }
        #pragma unroll
        for (int off = 16; off > 0; off >>= 1) {
            #pragma unroll
            for (int g = 0; g < NG; g++)
                acc[g] += __shfl_xor_sync(0xffffffffu, acc[g], off);
        }
        #pragma unroll
        for (int g = 0; g < NG; g++) acc[g] += bas[g];
        float mx = acc[0];
        #pragma unroll
        for (int g = 1; g < NG; g++) mx = fmaxf(mx, acc[g]);
        float s = 0.f, e_own = 0.f;
        #pragma unroll
        for (int g = 0; g < NG; g++) {
            float e = expf(acc[g] - mx);
            s += e;
            if (g == lane) e_own = e;
        }
        if (lane < NG) {
            float attn = e_own / s;
            float gv = genre[(size_t)b * NG + lane];
            w[(size_t)b * NG + lane] = (gv > 0.f) ? attn * gv : 0.f;
        }
    }
}

// ---------------------------------------------------------------------------
// tf32 GEMM (mma.sync, cp.async double-buffered, no per-fragment cvt):
//   C = act(A[M,K] @ W[K,N] + bias[N]), optionally tf32-round the output.
// Block tile 128x128, K-chunk 32, 8 warps (4x2), warp tile 32x64.
// blockIdx.z = genre. CONCAT mode: A is [X | R] along K.
// All A/W operands MUST be pre-rounded to tf32.
// ---------------------------------------------------------------------------
#define BM 128
#define BN 128
#define BK 32
#define LDAS 36
#define LDBS 136
#define ASZ (BM * LDAS)
#define WSZ (BK * LDBS)
#define GEMM_SMEM_BYTES ((2 * ASZ + 2 * WSZ) * 4)

template<int ACT, bool CONCAT, int ROUND>
__global__ __launch_bounds__(256, 2)
void gemm_tf32_kernel(const float* __restrict__ A, const float* __restrict__ Rp,
                      const float* __restrict__ W, const float* __restrict__ bias,
                      float* __restrict__ C,
                      int M, int N, int K, int lda,
                      long long sA, long long sW, long long sB, long long sC) {
    int g = blockIdx.z;
    A    += (size_t)g * sA;
    W    += (size_t)g * sW;
    bias += (size_t)g * sB;
    C    += (size_t)g * sC;

    extern __shared__ float sm[];
    float* As = sm;                 // [2][ASZ]
    float* Ws = sm + 2 * ASZ;       // [2][WSZ]
    uint32_t as_u = smem_u32(As);
    uint32_t ws_u = smem_u32(Ws);

    int tid  = threadIdx.x;
    int m0   = blockIdx.x * BM;
    int n0   = blockIdx.y * BN;
    int lane = tid & 31, warp = tid >> 5;
    int wm_base = (warp >> 1) * 32;
    int wn_base = (warp & 1) * 64;

    float acc[2][8][4];
    #pragma unroll
    for (int i = 0; i < 2; i++)
        #pragma unroll
        for (int j = 0; j < 8; j++)
            #pragma unroll
            for (int r = 0; r < 4; r++) acc[i][j][r] = 0.f;

    int ar = tid >> 3, ac = (tid & 7) * 4;     // A loader: 32 rows x 8 float4
    int wr = tid >> 5, wc = (tid & 31) * 4;    // W loader: 8 rows x 32 float4

    int nchunks = K / BK;

    auto stage = [&](int bsel, int k0) {
        // A tile [BM x BK]
        uint32_t abase = as_u + (uint32_t)bsel * ASZ * 4;
        #pragma unroll
        for (int rr = 0; rr < 4; rr++) {
            int r = ar + rr * 32;
            int grow = m0 + r;
            int gcol = k0 + ac;
            const float* src;
            if (!CONCAT) {
                src = A + (size_t)grow * lda + gcol;
            } else {
                src = (gcol < DIM) ? (A + (size_t)grow * DIM + gcol)
                                   : (Rp + (size_t)grow * HID + (gcol - DIM));
            }
            cp_async16(abase + (uint32_t)(r * LDAS + ac) * 4, src);
        }
        // W tile [BK x BN]
        uint32_t bbase = ws_u + (uint32_t)bsel * WSZ * 4;
        #pragma unroll
        for (int rr = 0; rr < 4; rr++) {
            int r = wr + rr * 8;
            cp_async16(bbase + (uint32_t)(r * LDBS + wc) * 4,
                       W + (size_t)(k0 + r) * N + n0 + wc);
        }
    };

    stage(0, 0);
    CP_COMMIT();

    for (int c = 0; c < nchunks; c++) {
        int cur = c & 1;
        if (c + 1 < nchunks) {
            stage(cur ^ 1, (c + 1) * BK);
            CP_COMMIT();
            CP_WAIT(1);
        } else {
            CP_WAIT(0);
        }
        __syncthreads();

        const float* Ab = As + cur * ASZ;
        const float* Wb = Ws + cur * WSZ;

        #pragma unroll
        for (int kk = 0; kk < 4; kk++) {
            int kb = kk * 8;
            uint32_t afr[2][4], bfr[8][2];
            #pragma unroll
            for (int wm = 0; wm < 2; wm++) {
                int r = wm_base + wm * 16 + (lane >> 2);
                int cidx = kb + (lane & 3);
                afr[wm][0] = __float_as_uint(Ab[r * LDAS + cidx]);
                afr[wm][1] = __float_as_uint(Ab[(r + 8) * LDAS + cidx]);
                afr[wm][2] = __float_as_uint(Ab[r * LDAS + cidx + 4]);
                afr[wm][3] = __float_as_uint(Ab[(r + 8) * LDAS + cidx + 4]);
            }
            #pragma unroll
            for (int wn = 0; wn < 8; wn++) {
                int ccol = wn_base + wn * 8 + (lane >> 2);
                int rrow = kb + (lane & 3);
                bfr[wn][0] = __float_as_uint(Wb[rrow * LDBS + ccol]);
                bfr[wn][1] = __float_as_uint(Wb[(rrow + 4) * LDBS + ccol]);
            }
            #pragma unroll
            for (int wm = 0; wm < 2; wm++)
                #pragma unroll
                for (int wn = 0; wn < 8; wn++)
                    mma8(acc[wm][wn], afr[wm], bfr[wn]);
        }
        __syncthreads();
    }

    // ---- epilogue: + bias, optional relu, optional tf32 round, write ----
    #pragma unroll
    for (int wm = 0; wm < 2; wm++) {
        int r0 = m0 + wm_base + wm * 16 + (lane >> 2);
        #pragma unroll
        for (int wn = 0; wn < 8; wn++) {
            int c0 = n0 + wn_base + wn * 8 + 2 * (lane & 3);
            float b0 = bias[c0], b1v = bias[c0 + 1];
            float v0 = acc[wm][wn][0] + b0;
            float v1 = acc[wm][wn][1] + b1v;
            float v2 = acc[wm][wn][2] + b0;
            float v3 = acc[wm][wn][3] + b1v;
            if (ACT) {
                v0 = fmaxf(v0, 0.f); v1 = fmaxf(v1, 0.f);
                v2 = fmaxf(v2, 0.f); v3 = fmaxf(v3, 0.f);
            }
            if (ROUND) {
                v0 = round_tf32(v0); v1 = round_tf32(v1);
                v2 = round_tf32(v2); v3 = round_tf32(v3);
            }
            float2 p0 = make_float2(v0, v1);
            float2 p1 = make_float2(v2, v3);
            *(float2*)(C + (size_t)r0 * N + c0)       = p0;
            *(float2*)(C + (size_t)(r0 + 8) * N + c0) = p1;
        }
    }
}

// ---------------------------------------------------------------------------
// Weighted reduce: R[b,:] = sum_g w[b,g] * H3[g,b,:]  (tf32-rounded output)
// ---------------------------------------------------------------------------
__global__ __launch_bounds__(256)
void reduce_kernel(const float* __restrict__ H3, const float* __restrict__ w,
                   float* __restrict__ R) {
    int idx = blockIdx.x * blockDim.x + threadIdx.x;
    int b = idx >> 5;
    float4 r = make_float4(0.f, 0.f, 0.f, 0.f);
    const float4* H = (const float4*)H3;
    #pragma unroll
    for (int g = 0; g < NG; g++) {
        float wv = w[(size_t)b * NG + g];
        if (wv != 0.f) {
            float4 h = H[(size_t)g * (BATCH * 32) + idx];
            r.x += wv * h.x; r.y += wv * h.y;
            r.z += wv * h.z; r.w += wv * h.w;
        }
    }
    r.x = round_tf32(r.x); r.y = round_tf32(r.y);
    r.z = round_tf32(r.z); r.w = round_tf32(r.w);
    ((float4*)R)[idx] = r;
}

// ---------------------------------------------------------------------------
// Launch
// ---------------------------------------------------------------------------
extern "C" void kernel_launch(void* const* d_in, const int* in_sizes, int n_in,
                              void* d_out, int out_size) {
    (void)in_sizes; (void)n_in; (void)out_size;
    const float* X     = (const float*)d_in[0];
    const float* genre = (const float*)d_in[1];
    const float* W1    = (const float*)d_in[2];
    const float* b1    = (const float*)d_in[3];
    const float* W2    = (const float*)d_in[4];
    const float* b2    = (const float*)d_in[5];
    const float* W3    = (const float*)d_in[6];
    const float* b3    = (const float*)d_in[7];
    const float* Wa    = (const float*)d_in[8];
    const float* ba    = (const float*)d_in[9];
    const float* Wagg  = (const float*)d_in[10];
    const float* bagg  = (const float*)d_in[11];
    float* out = (float*)d_out;

    float *w, *buf1, *H2, *R, *Xr, *W1r, *W2r, *W3r, *Waggr;
    cudaGetSymbolAddress((void**)&w,     g_w);
    cudaGetSymbolAddress((void**)&buf1,  g_buf1);
    cudaGetSymbolAddress((void**)&H2,    g_H2);
    cudaGetSymbolAddress((void**)&R,     g_R);
    cudaGetSymbolAddress((void**)&Xr,    g_Xr);
    cudaGetSymbolAddress((void**)&W1r,   g_W1r);
    cudaGetSymbolAddress((void**)&W2r,   g_W2r);
    cudaGetSymbolAddress((void**)&W3r,   g_W3r);
    cudaGetSymbolAddress((void**)&Waggr, g_Waggr);

    static bool attr_done = false;
    if (!attr_done) {
        cudaFuncSetAttribute(gemm_tf32_kernel<1, false, 1>,
                             cudaFuncAttributeMaxDynamicSharedMemorySize, GEMM_SMEM_BYTES);
        cudaFuncSetAttribute(gemm_tf32_kernel<0, false, 0>,
                             cudaFuncAttributeMaxDynamicSharedMemorySize, GEMM_SMEM_BYTES);
        cudaFuncSetAttribute(gemm_tf32_kernel<1, true, 0>,
                             cudaFuncAttributeMaxDynamicSharedMemorySize, GEMM_SMEM_BYTES);
        attr_done = true;
    }

    // 0) prep: tf32-round all GEMM operands
    round_kernel<<<512, 256>>>(X,    Xr,    BATCH * DIM / 4);
    round_kernel<<<512, 256>>>(W1,   W1r,   NG * DIM * HID2 / 4);
    round_kernel<<<256, 256>>>(W2,   W2r,   NG * HID2 * HID / 4);
    round_kernel<<<128, 256>>>(W3,   W3r,   NG * HID * HID / 4);
    round_kernel<<<128, 256>>>(Wagg, Waggr, DAGG * DIM / 4);

    // 1) attention weights (masked)
    attn_kernel<<<BATCH / 64, 256>>>(X, genre, Wa, ba, w);

    // 2) H1 = relu(Xr @ W1r[g] + b1[g])  -> rounded
    gemm_tf32_kernel<1, false, 1><<<dim3(BATCH / BM, HID2 / BN, NG), 256, GEMM_SMEM_BYTES>>>(
        Xr, nullptr, W1r, b1, buf1,
        BATCH, HID2, DIM, DIM,
        0LL, (long long)DIM * HID2, HID2, (long long)BATCH * HID2);

    // 3) H2 = relu(H1 @ W2r[g] + b2[g]) -> rounded
    gemm_tf32_kernel<1, false, 1><<<dim3(BATCH / BM, 1, NG), 256, GEMM_SMEM_BYTES>>>(
        buf1, nullptr, W2r, b2, H2,
        BATCH, HID, HID2, HID2,
        (long long)BATCH * HID2, (long long)HID2 * HID, HID, (long long)BATCH * HID);

    // 4) H3 = H2 @ W3r[g] + b3[g]   (reuse buf1; fp32 out)
    gemm_tf32_kernel<0, false, 0><<<dim3(BATCH / BM, 1, NG), 256, GEMM_SMEM_BYTES>>>(
        H2, nullptr, W3r, b3, buf1,
        BATCH, HID, HID, HID,
        (long long)BATCH * HID, (long long)HID * HID, HID, (long long)BATCH * HID);

    // 5) R = sum_g w .* H3  -> rounded
    reduce_kernel<<<(BATCH * 32) / 256, 256>>>(buf1, w, R);

    // 6) out = relu([Xr, R] @ Waggr + bagg)
    gemm_tf32_kernel<1, true, 0><<<dim3(BATCH / BM, DIM / BN, 1), 256, GEMM_SMEM_BYTES>>>(
        Xr, R, Waggr, bagg, out,
        BATCH, DIM, DAGG, DAGG,
        0LL, 0LL, 0LL, 0LL);
}

// round 5
// speedup vs baseline: 1.8980x; 1.5705x over previous
#include <cuda_runtime.h>
#include <cstdint>
#include <cstddef>

// Problem constants
#define BATCH   16384
#define DIM     512
#define HID     128     // H
#define HID2    256     // 2H
#define NG      18
#define DAGG    640     // D + H

// ---------------------------------------------------------------------------
// Scratch (device globals; allocation-free rule)
// ---------------------------------------------------------------------------
__device__ float g_w[(size_t)BATCH * NG];                    // masked attention weights
__device__ float g_buf1[(size_t)NG * BATCH * HID2];          // H1c, later reused for H3c
__device__ float g_H2[(size_t)NG * BATCH * HID];             // H2c
__device__ float g_R[(size_t)BATCH * HID];                   // refinements
__device__ float g_Xr[(size_t)BATCH * DIM];                  // X rounded to tf32
__device__ float g_W1r[(size_t)NG * DIM * HID2];             // rounded weights
__device__ float g_W2r[(size_t)NG * HID2 * HID];
__device__ float g_W3r[(size_t)NG * HID * HID];
__device__ float g_Waggr[(size_t)DAGG * DIM];
__device__ int   g_counts[32];                               // members per genre
__device__ int   g_idx[(size_t)NG * BATCH];                  // genre -> member rows
__device__ int   g_pos[(size_t)BATCH * NG];                  // (b,g) -> slot

// ---------------------------------------------------------------------------
// Helpers
// ---------------------------------------------------------------------------
__device__ __forceinline__ uint32_t f2tf(float f) {
    uint32_t u;
    asm("cvt.rna.tf32.f32 %0, %1;" : "=r"(u) : "f"(f));
    return u;
}
__device__ __forceinline__ float round_tf32(float f) {
    return __uint_as_float(f2tf(f));
}
__device__ __forceinline__ uint32_t smem_u32(const void* p) {
    uint32_t a;
    asm("{ .reg .u64 t; cvta.to.shared.u64 t, %1; cvt.u32.u64 %0, t; }" : "=r"(a) : "l"(p));
    return a;
}
__device__ __forceinline__ void cp_async16(uint32_t dst, const void* src) {
    asm volatile("cp.async.cg.shared.global [%0], [%1], 16;" :: "r"(dst), "l"(src) : "memory");
}
#define CP_COMMIT() asm volatile("cp.async.commit_group;" ::: "memory")
#define CP_WAIT(n)  asm volatile("cp.async.wait_group %0;" :: "n"(n) : "memory")

__device__ __forceinline__ void mma8(float* d, const uint32_t* a, const uint32_t* b) {
    asm volatile(
        "mma.sync.aligned.m16n8k8.row.col.f32.tf32.tf32.f32 "
        "{%0,%1,%2,%3}, {%4,%5,%6,%7}, {%8,%9}, {%0,%1,%2,%3};"
        : "+f"(d[0]), "+f"(d[1]), "+f"(d[2]), "+f"(d[3])
        : "r"(a[0]), "r"(a[1]), "r"(a[2]), "r"(a[3]), "r"(b[0]), "r"(b[1]));
}

// ---------------------------------------------------------------------------
// Prep: tf32 rounding (grid-stride float4)
// ---------------------------------------------------------------------------
__global__ __launch_bounds__(256)
void round_kernel(const float* __restrict__ in, float* __restrict__ out, int n4) {
    int i = blockIdx.x * 256 + threadIdx.x;
    int stride = gridDim.x * 256;
    for (; i < n4; i += stride) {
        float4 v = ((const float4*)in)[i];
        v.x = round_tf32(v.x); v.y = round_tf32(v.y);
        v.z = round_tf32(v.z); v.w = round_tf32(v.w);
        ((float4*)out)[i] = v;
    }
}

// ---------------------------------------------------------------------------
// Membership compaction
// ---------------------------------------------------------------------------
__global__ __launch_bounds__(256)
void zero_kernel(int* __restrict__ counts, int* __restrict__ idxArr) {
    int t = blockIdx.x * 256 + threadIdx.x;
    if (t < 32) counts[t] = 0;
    int n4 = NG * BATCH / 4;
    for (int i = t; i < n4; i += gridDim.x * 256)
        ((int4*)idxArr)[i] = make_int4(0, 0, 0, 0);
}

__global__ __launch_bounds__(256)
void compact_kernel(const float* __restrict__ genre, int* __restrict__ counts,
                    int* __restrict__ idxArr, int* __restrict__ pos) {
    int t = blockIdx.x * 256 + threadIdx.x;   // over NG * BATCH, g-major
    int g = t >> 14;                          // BATCH = 2^14
    int b = t & (BATCH - 1);
    float gv = genre[(size_t)b * NG + g];
    unsigned mask = __ballot_sync(0xffffffffu, gv > 0.f);
    int lane = threadIdx.x & 31;
    int base = 0;
    if (lane == 0 && mask) base = atomicAdd(&counts[g], __popc(mask));
    base = __shfl_sync(0xffffffffu, base, 0);
    if (gv > 0.f) {
        int slot = base + __popc(mask & ((1u << lane) - 1u));
        idxArr[(size_t)g * BATCH + slot] = b;
        pos[(size_t)b * NG + g] = slot;
    }
}

// ---------------------------------------------------------------------------
// Attention kernel: logits = X @ Wa + ba, softmax over G, mask by membership
// ---------------------------------------------------------------------------
__global__ __launch_bounds__(256)
void attn_kernel(const float* __restrict__ X, const float* __restrict__ genre,
                 const float* __restrict__ Wa, const float* __restrict__ ba,
                 float* __restrict__ w) {
    __shared__ float Was[DIM * 19];
    __shared__ float bas[32];
    int tid = threadIdx.x;
    for (int i = tid; i < DIM * NG; i += 256) {
        int d = i / NG, g = i % NG;
        Was[d * 19 + g] = Wa[i];
    }
    if (tid < NG) bas[tid] = ba[tid];
    __syncthreads();

    int warp = tid >> 5, lane = tid & 31;
    for (int it = 0; it < 8; ++it) {
        int b = blockIdx.x * 64 + it * 8 + warp;
        float acc[NG];
        #pragma unroll
        for (int g = 0; g < NG; g++) acc[g] = 0.f;
        #pragma unroll
        for (int i = 0; i < 16; i++) {
            int d = 32 * i + lane;
            float xv = X[(size_t)b * DIM + d];
            const float* wrow = &Was[d * 19];
            #pragma unroll
            for (int g = 0; g < NG; g++) acc[g] += xv * wrow[g];
        }
        #pragma unroll
        for (int off = 16; off > 0; off >>= 1) {
            #pragma unroll
            for (int g = 0; g < NG; g++)
                acc[g] += __shfl_xor_sync(0xffffffffu, acc[g], off);
        }
        #pragma unroll
        for (int g = 0; g < NG; g++) acc[g] += bas[g];
        float mx = acc[0];
        #pragma unroll
        for (int g = 1; g < NG; g++) mx = fmaxf(mx, acc[g]);
        float s = 0.f, e_own = 0.f;
        #pragma unroll
        for (int g = 0; g < NG; g++) {
            float e = expf(acc[g] - mx);
            s += e;
            if (g == lane) e_own = e;
        }
        if (lane < NG) {
            float attn = e_own / s;
            float gv = genre[(size_t)b * NG + lane];
            w[(size_t)b * NG + lane] = (gv > 0.f) ? attn * gv : 0.f;
        }
    }
}

// ---------------------------------------------------------------------------
// tf32 GEMM (mma.sync, cp.async double-buffered, pre-rounded operands).
// MODE: 1 = gather-A rows via idx + early-exit by counts;
//       2 = dense + early-exit by counts; 3 = concat [X|R] along K.
// Block tile 128x128, K-chunk 32, 8 warps (4x2), warp tile 32x64.
// ---------------------------------------------------------------------------
#define BM 128
#define BN 128
#define BK 32
#define LDAS 36
#define LDBS 136
#define ASZ (BM * LDAS)
#define WSZ (BK * LDBS)
#define GEMM_SMEM_BYTES ((2 * ASZ + 2 * WSZ) * 4)

template<int ACT, int ROUND, int MODE>
__global__ __launch_bounds__(256, 2)
void gemm_tf32_kernel(const float* __restrict__ A, const float* __restrict__ Rp,
                      const float* __restrict__ W, const float* __restrict__ bias,
                      float* __restrict__ C,
                      int M, int N, int K, int lda,
                      long long sA, long long sW, long long sB, long long sC,
                      const int* __restrict__ idxArr, const int* __restrict__ counts) {
    int g = blockIdx.z;
    int m0 = blockIdx.x * BM;
    if (MODE == 1 || MODE == 2) {
        if (m0 >= counts[g]) return;
    }
    A    += (size_t)g * sA;
    W    += (size_t)g * sW;
    bias += (size_t)g * sB;
    C    += (size_t)g * sC;
    const int* gidx = idxArr + (size_t)g * BATCH;

    extern __shared__ float sm[];
    float* As = sm;                 // [2][ASZ]
    float* Ws = sm + 2 * ASZ;       // [2][WSZ]
    uint32_t as_u = smem_u32(As);
    uint32_t ws_u = smem_u32(Ws);

    int tid  = threadIdx.x;
    int n0   = blockIdx.y * BN;
    int lane = tid & 31, warp = tid >> 5;
    int wm_base = (warp >> 1) * 32;
    int wn_base = (warp & 1) * 64;

    float acc[2][8][4];
    #pragma unroll
    for (int i = 0; i < 2; i++)
        #pragma unroll
        for (int j = 0; j < 8; j++)
            #pragma unroll
            for (int r = 0; r < 4; r++) acc[i][j][r] = 0.f;

    int ar = tid >> 3, ac = (tid & 7) * 4;     // A loader: 32 rows x 8 float4
    int wr = tid >> 5, wc = (tid & 31) * 4;    // W loader: 8 rows x 32 float4

    // Pre-resolve gathered row pointers for this thread's 4 A rows
    const float* arow_ptr[4];
    #pragma unroll
    for (int rr = 0; rr < 4; rr++) {
        int r = ar + rr * 32;
        int grow = m0 + r;
        if (MODE == 1) {
            int srcrow = gidx[grow];
            arow_ptr[rr] = A + (size_t)srcrow * lda;
        } else {
            arow_ptr[rr] = A + (size_t)grow * lda;
        }
    }

    int nchunks = K / BK;

    auto stage = [&](int bsel, int k0) {
        uint32_t abase = as_u + (uint32_t)bsel * ASZ * 4;
        #pragma unroll
        for (int rr = 0; rr < 4; rr++) {
            int r = ar + rr * 32;
            int gcol = k0 + ac;
            const float* src;
            if (MODE == 3) {
                int grow = m0 + r;
                src = (gcol < DIM) ? (A + (size_t)grow * DIM + gcol)
                                   : (Rp + (size_t)grow * HID + (gcol - DIM));
            } else {
                src = arow_ptr[rr] + gcol;
            }
            cp_async16(abase + (uint32_t)(r * LDAS + ac) * 4, src);
        }
        uint32_t bbase = ws_u + (uint32_t)bsel * WSZ * 4;
        #pragma unroll
        for (int rr = 0; rr < 4; rr++) {
            int r = wr + rr * 8;
            cp_async16(bbase + (uint32_t)(r * LDBS + wc) * 4,
                       W + (size_t)(k0 + r) * N + n0 + wc);
        }
    };

    stage(0, 0);
    CP_COMMIT();

    for (int c = 0; c < nchunks; c++) {
        int cur = c & 1;
        if (c + 1 < nchunks) {
            stage(cur ^ 1, (c + 1) * BK);
            CP_COMMIT();
            CP_WAIT(1);
        } else {
            CP_WAIT(0);
        }
        __syncthreads();

        const float* Ab = As + cur * ASZ;
        const float* Wb = Ws + cur * WSZ;

        #pragma unroll
        for (int kk = 0; kk < 4; kk++) {
            int kb = kk * 8;
            uint32_t afr[2][4], bfr[8][2];
            #pragma unroll
            for (int wm = 0; wm < 2; wm++) {
                int r = wm_base + wm * 16 + (lane >> 2);
                int cidx = kb + (lane & 3);
                afr[wm][0] = __float_as_uint(Ab[r * LDAS + cidx]);
                afr[wm][1] = __float_as_uint(Ab[(r + 8) * LDAS + cidx]);
                afr[wm][2] = __float_as_uint(Ab[r * LDAS + cidx + 4]);
                afr[wm][3] = __float_as_uint(Ab[(r + 8) * LDAS + cidx + 4]);
            }
            #pragma unroll
            for (int wn = 0; wn < 8; wn++) {
                int ccol = wn_base + wn * 8 + (lane >> 2);
                int rrow = kb + (lane & 3);
                bfr[wn][0] = __float_as_uint(Wb[rrow * LDBS + ccol]);
                bfr[wn][1] = __float_as_uint(Wb[(rrow + 4) * LDBS + ccol]);
            }
            #pragma unroll
            for (int wm = 0; wm < 2; wm++)
                #pragma unroll
                for (int wn = 0; wn < 8; wn++)
                    mma8(acc[wm][wn], afr[wm], bfr[wn]);
        }
        __syncthreads();
    }

    // ---- epilogue: + bias, optional relu, optional tf32 round, write ----
    #pragma unroll
    for (int wm = 0; wm < 2; wm++) {
        int r0 = m0 + wm_base + wm * 16 + (lane >> 2);
        #pragma unroll
        for (int wn = 0; wn < 8; wn++) {
            int c0 = n0 + wn_base + wn * 8 + 2 * (lane & 3);
            float b0 = bias[c0], b1v = bias[c0 + 1];
            float v0 = acc[wm][wn][0] + b0;
            float v1 = acc[wm][wn][1] + b1v;
            float v2 = acc[wm][wn][2] + b0;
            float v3 = acc[wm][wn][3] + b1v;
            if (ACT) {
                v0 = fmaxf(v0, 0.f); v1 = fmaxf(v1, 0.f);
                v2 = fmaxf(v2, 0.f); v3 = fmaxf(v3, 0.f);
            }
            if (ROUND) {
                v0 = round_tf32(v0); v1 = round_tf32(v1);
                v2 = round_tf32(v2); v3 = round_tf32(v3);
            }
            float2 p0 = make_float2(v0, v1);
            float2 p1 = make_float2(v2, v3);
            *(float2*)(C + (size_t)r0 * N + c0)       = p0;
            *(float2*)(C + (size_t)(r0 + 8) * N + c0) = p1;
        }
    }
}

// ---------------------------------------------------------------------------
// Weighted reduce (compacted): R[b,:] = sum_g w[b,g] * H3c[g, pos[b,g], :]
// ---------------------------------------------------------------------------
__global__ __launch_bounds__(256)
void reduce_kernel(const float* __restrict__ H3, const float* __restrict__ w,
                   const int* __restrict__ pos, float* __restrict__ R) {
    int idx = blockIdx.x * blockDim.x + threadIdx.x;   // over BATCH * 32 float4s
    int b = idx >> 5;
    int off = idx & 31;
    float4 r = make_float4(0.f, 0.f, 0.f, 0.f);
    const float4* H = (const float4*)H3;
    #pragma unroll
    for (int g = 0; g < NG; g++) {
        float wv = w[(size_t)b * NG + g];
        if (wv != 0.f) {
            int slot = pos[(size_t)b * NG + g];
            float4 h = H[((size_t)g * BATCH + slot) * 32 + off];
            r.x += wv * h.x; r.y += wv * h.y;
            r.z += wv * h.z; r.w += wv * h.w;
        }
    }
    r.x = round_tf32(r.x); r.y = round_tf32(r.y);
    r.z = round_tf32(r.z); r.w = round_tf32(r.w);
    ((float4*)R)[idx] = r;
}

// ---------------------------------------------------------------------------
// Launch
// ---------------------------------------------------------------------------
extern "C" void kernel_launch(void* const* d_in, const int* in_sizes, int n_in,
                              void* d_out, int out_size) {
    (void)in_sizes; (void)n_in; (void)out_size;
    const float* X     = (const float*)d_in[0];
    const float* genre = (const float*)d_in[1];
    const float* W1    = (const float*)d_in[2];
    const float* b1    = (const float*)d_in[3];
    const float* W2    = (const float*)d_in[4];
    const float* b2    = (const float*)d_in[5];
    const float* W3    = (const float*)d_in[6];
    const float* b3    = (const float*)d_in[7];
    const float* Wa    = (const float*)d_in[8];
    const float* ba    = (const float*)d_in[9];
    const float* Wagg  = (const float*)d_in[10];
    const float* bagg  = (const float*)d_in[11];
    float* out = (float*)d_out;

    float *w, *buf1, *H2, *R, *Xr, *W1r, *W2r, *W3r, *Waggr;
    int *counts, *idxArr, *pos;
    cudaGetSymbolAddress((void**)&w,      g_w);
    cudaGetSymbolAddress((void**)&buf1,   g_buf1);
    cudaGetSymbolAddress((void**)&H2,     g_H2);
    cudaGetSymbolAddress((void**)&R,      g_R);
    cudaGetSymbolAddress((void**)&Xr,     g_Xr);
    cudaGetSymbolAddress((void**)&W1r,    g_W1r);
    cudaGetSymbolAddress((void**)&W2r,    g_W2r);
    cudaGetSymbolAddress((void**)&W3r,    g_W3r);
    cudaGetSymbolAddress((void**)&Waggr,  g_Waggr);
    cudaGetSymbolAddress((void**)&counts, g_counts);
    cudaGetSymbolAddress((void**)&idxArr, g_idx);
    cudaGetSymbolAddress((void**)&pos,    g_pos);

    // Unconditional (idempotent, host-side, not captured) — no static guards.
    cudaFuncSetAttribute(gemm_tf32_kernel<1, 1, 1>,
                         cudaFuncAttributeMaxDynamicSharedMemorySize, GEMM_SMEM_BYTES);
    cudaFuncSetAttribute(gemm_tf32_kernel<1, 1, 2>,
                         cudaFuncAttributeMaxDynamicSharedMemorySize, GEMM_SMEM_BYTES);
    cudaFuncSetAttribute(gemm_tf32_kernel<0, 0, 2>,
                         cudaFuncAttributeMaxDynamicSharedMemorySize, GEMM_SMEM_BYTES);
    cudaFuncSetAttribute(gemm_tf32_kernel<1, 0, 3>,
                         cudaFuncAttributeMaxDynamicSharedMemorySize, GEMM_SMEM_BYTES);

    // 0) prep: tf32-round all GEMM operands; build membership compaction
    round_kernel<<<512, 256>>>(X,    Xr,    BATCH * DIM / 4);
    round_kernel<<<512, 256>>>(W1,   W1r,   NG * DIM * HID2 / 4);
    round_kernel<<<256, 256>>>(W2,   W2r,   NG * HID2 * HID / 4);
    round_kernel<<<128, 256>>>(W3,   W3r,   NG * HID * HID / 4);
    round_kernel<<<128, 256>>>(Wagg, Waggr, DAGG * DIM / 4);
    zero_kernel<<<288, 256>>>(counts, idxArr);
    compact_kernel<<<NG * BATCH / 256, 256>>>(genre, counts, idxArr, pos);

    // 1) attention weights (masked)
    attn_kernel<<<BATCH / 64, 256>>>(X, genre, Wa, ba, w);

    // 2) H1c = relu(gather(Xr) @ W1r[g] + b1[g])  [compacted rows]
    gemm_tf32_kernel<1, 1, 1><<<dim3(BATCH / BM, HID2 / BN, NG), 256, GEMM_SMEM_BYTES>>>(
        Xr, nullptr, W1r, b1, buf1,
        BATCH, HID2, DIM, DIM,
        0LL, (long long)DIM * HID2, HID2, (long long)BATCH * HID2,
        idxArr, counts);

    // 3) H2c = relu(H1c @ W2r[g] + b2[g])
    gemm_tf32_kernel<1, 1, 2><<<dim3(BATCH / BM, 1, NG), 256, GEMM_SMEM_BYTES>>>(
        buf1, nullptr, W2r, b2, H2,
        BATCH, HID, HID2, HID2,
        (long long)BATCH * HID2, (long long)HID2 * HID, HID, (long long)BATCH * HID,
        idxArr, counts);

    // 4) H3c = H2c @ W3r[g] + b3[g]   (reuse buf1)
    gemm_tf32_kernel<0, 0, 2><<<dim3(BATCH / BM, 1, NG), 256, GEMM_SMEM_BYTES>>>(
        H2, nullptr, W3r, b3, buf1,
        BATCH, HID, HID, HID,
        (long long)BATCH * HID, (long long)HID * HID, HID, (long long)BATCH * HID,
        idxArr, counts);

    // 5) R = sum_g w .* H3c[pos]
    reduce_kernel<<<(BATCH * 32) / 256, 256>>>(buf1, w, pos, R);

    // 6) out = relu([Xr, R] @ Waggr + bagg)
    gemm_tf32_kernel<1, 0, 3><<<dim3(BATCH / BM, DIM / BN, 1), 256, GEMM_SMEM_BYTES>>>(
        Xr, R, Waggr, bagg, out,
        BATCH, DIM, DAGG, DAGG,
        0LL, 0LL, 0LL, 0LL,
        idxArr, counts);
}

// round 6
// speedup vs baseline: 1.9048x; 1.0035x over previous
#include <cuda_runtime.h>
#include <cstdint>
#include <cstddef>

// Problem constants
#define BATCH   16384
#define DIM     512
#define HID     128     // H
#define HID2    256     // 2H
#define NG      18
#define DAGG    640     // D + H

// ---------------------------------------------------------------------------
// Scratch (device globals; allocation-free rule)
// ---------------------------------------------------------------------------
__device__ float g_w[(size_t)BATCH * NG];                    // masked attention weights
__device__ float g_buf1[(size_t)NG * BATCH * HID2];          // H1c, later reused for H3c
__device__ float g_H2[(size_t)NG * BATCH * HID];             // H2c
__device__ float g_R[(size_t)BATCH * HID];                   // refinements
__device__ float g_Xr[(size_t)BATCH * DIM];                  // X rounded to tf32
__device__ float g_W1r[(size_t)NG * DIM * HID2];             // rounded weights
__device__ float g_W2r[(size_t)NG * HID2 * HID];
__device__ float g_W3r[(size_t)NG * HID * HID];
__device__ float g_Waggr[(size_t)DAGG * DIM];
__device__ int   g_counts[32];                               // members per genre
__device__ int   g_idx[(size_t)NG * BATCH];                  // genre -> member rows
__device__ int   g_pos[(size_t)BATCH * NG];                  // (b,g) -> slot

// ---------------------------------------------------------------------------
// Helpers
// ---------------------------------------------------------------------------
__device__ __forceinline__ uint32_t f2tf(float f) {
    uint32_t u;
    asm("cvt.rna.tf32.f32 %0, %1;" : "=r"(u) : "f"(f));
    return u;
}
__device__ __forceinline__ float round_tf32(float f) {
    return __uint_as_float(f2tf(f));
}
__device__ __forceinline__ uint32_t smem_u32(const void* p) {
    uint32_t a;
    asm("{ .reg .u64 t; cvta.to.shared.u64 t, %1; cvt.u32.u64 %0, t; }" : "=r"(a) : "l"(p));
    return a;
}
__device__ __forceinline__ void cp_async16(uint32_t dst, const void* src) {
    asm volatile("cp.async.cg.shared.global [%0], [%1], 16;" :: "r"(dst), "l"(src) : "memory");
}
#define CP_COMMIT() asm volatile("cp.async.commit_group;" ::: "memory")
#define CP_WAIT(n)  asm volatile("cp.async.wait_group %0;" :: "n"(n) : "memory")

__device__ __forceinline__ void mma8(float* d, const uint32_t* a, const uint32_t* b) {
    asm volatile(
        "mma.sync.aligned.m16n8k8.row.col.f32.tf32.tf32.f32 "
        "{%0,%1,%2,%3}, {%4,%5,%6,%7}, {%8,%9}, {%0,%1,%2,%3};"
        : "+f"(d[0]), "+f"(d[1]), "+f"(d[2]), "+f"(d[3])
        : "r"(a[0]), "r"(a[1]), "r"(a[2]), "r"(a[3]), "r"(b[0]), "r"(b[1]));
}

// ---------------------------------------------------------------------------
// Prep: tf32 rounding (grid-stride float4)
// ---------------------------------------------------------------------------
__global__ __launch_bounds__(256)
void round_kernel(const float* __restrict__ in, float* __restrict__ out, int n4) {
    int i = blockIdx.x * 256 + threadIdx.x;
    int stride = gridDim.x * 256;
    for (; i < n4; i += stride) {
        float4 v = ((const float4*)in)[i];
        v.x = round_tf32(v.x); v.y = round_tf32(v.y);
        v.z = round_tf32(v.z); v.w = round_tf32(v.w);
        ((float4*)out)[i] = v;
    }
}

// ---------------------------------------------------------------------------
// Membership compaction
// ---------------------------------------------------------------------------
__global__ __launch_bounds__(256)
void zero_kernel(int* __restrict__ counts, int* __restrict__ idxArr) {
    int t = blockIdx.x * 256 + threadIdx.x;
    if (t < 32) counts[t] = 0;
    int n4 = NG * BATCH / 4;
    for (int i = t; i < n4; i += gridDim.x * 256)
        ((int4*)idxArr)[i] = make_int4(0, 0, 0, 0);
}

__global__ __launch_bounds__(256)
void compact_kernel(const float* __restrict__ genre, int* __restrict__ counts,
                    int* __restrict__ idxArr, int* __restrict__ pos) {
    int t = blockIdx.x * 256 + threadIdx.x;   // over NG * BATCH, g-major
    int g = t >> 14;                          // BATCH = 2^14
    int b = t & (BATCH - 1);
    float gv = genre[(size_t)b * NG + g];
    unsigned mask = __ballot_sync(0xffffffffu, gv > 0.f);
    int lane = threadIdx.x & 31;
    int base = 0;
    if (lane == 0 && mask) base = atomicAdd(&counts[g], __popc(mask));
    base = __shfl_sync(0xffffffffu, base, 0);
    if (gv > 0.f) {
        int slot = base + __popc(mask & ((1u << lane) - 1u));
        idxArr[(size_t)g * BATCH + slot] = b;
        pos[(size_t)b * NG + g] = slot;
    }
}

// ---------------------------------------------------------------------------
// Attention kernel: logits = X @ Wa + ba, softmax over G, mask by membership
// ---------------------------------------------------------------------------
__global__ __launch_bounds__(256)
void attn_kernel(const float* __restrict__ X, const float* __restrict__ genre,
                 const float* __restrict__ Wa, const float* __restrict__ ba,
                 float* __restrict__ w) {
    __shared__ float Was[DIM * 19];
    __shared__ float bas[32];
    int tid = threadIdx.x;
    for (int i = tid; i < DIM * NG; i += 256) {
        int d = i / NG, g = i % NG;
        Was[d * 19 + g] = Wa[i];
    }
    if (tid < NG) bas[tid] = ba[tid];
    __syncthreads();

    int warp = tid >> 5, lane = tid & 31;
    for (int it = 0; it < 8; ++it) {
        int b = blockIdx.x * 64 + it * 8 + warp;
        float acc[NG];
        #pragma unroll
        for (int g = 0; g < NG; g++) acc[g] = 0.f;
        #pragma unroll
        for (int i = 0; i < 16; i++) {
            int d = 32 * i + lane;
            float xv = X[(size_t)b * DIM + d];
            const float* wrow = &Was[d * 19];
            #pragma unroll
            for (int g = 0; g < NG; g++) acc[g] += xv * wrow[g];
        }
        #pragma unroll
        for (int off = 16; off > 0; off >>= 1) {
            #pragma unroll
            for (int g = 0; g < NG; g++)
                acc[g] += __shfl_xor_sync(0xffffffffu, acc[g], off);
        }
        #pragma unroll
        for (int g = 0; g < NG; g++) acc[g] += bas[g];
        float mx = acc[0];
        #pragma unroll
        for (int g = 1; g < NG; g++) mx = fmaxf(mx, acc[g]);
        float s = 0.f, e_own = 0.f;
        #pragma unroll
        for (int g = 0; g < NG; g++) {
            float e = expf(acc[g] - mx);
            s += e;
            if (g == lane) e_own = e;
        }
        if (lane < NG) {
            float attn = e_own / s;
            float gv = genre[(size_t)b * NG + lane];
            w[(size_t)b * NG + lane] = (gv > 0.f) ? attn * gv : 0.f;
        }
    }
}

// ---------------------------------------------------------------------------
// tf32 GEMM (mma.sync, cp.async double-buffered, pre-rounded operands).
// MODE: 1 = gather-A rows via idx + early-exit by counts;
//       2 = dense + early-exit by counts; 3 = concat [X|R] along K.
// Block tile 128x128, K-chunk 32, 8 warps (4x2), warp tile 32x64.
// ---------------------------------------------------------------------------
#define BM 128
#define BN 128
#define BK 32
#define LDAS 36
#define LDBS 136
#define ASZ (BM * LDAS)
#define WSZ (BK * LDBS)
#define GEMM_SMEM_BYTES ((2 * ASZ + 2 * WSZ) * 4)

template<int ACT, int ROUND, int MODE>
__global__ __launch_bounds__(256, 2)
void gemm_tf32_kernel(const float* __restrict__ A, const float* __restrict__ Rp,
                      const float* __restrict__ W, const float* __restrict__ bias,
                      float* __restrict__ C,
                      int M, int N, int K, int lda,
                      long long sA, long long sW, long long sB, long long sC,
                      const int* __restrict__ idxArr, const int* __restrict__ counts) {
    int g = blockIdx.z;
    int m0 = blockIdx.x * BM;
    if (MODE == 1 || MODE == 2) {
        if (m0 >= counts[g]) return;
    }
    A    += (size_t)g * sA;
    W    += (size_t)g * sW;
    bias += (size_t)g * sB;
    C    += (size_t)g * sC;
    const int* gidx = idxArr + (size_t)g * BATCH;

    extern __shared__ float sm[];
    float* As = sm;                 // [2][ASZ]
    float* Ws = sm + 2 * ASZ;       // [2][WSZ]
    uint32_t as_u = smem_u32(As);
    uint32_t ws_u = smem_u32(Ws);

    int tid  = threadIdx.x;
    int n0   = blockIdx.y * BN;
    int lane = tid & 31, warp = tid >> 5;
    int wm_base = (warp >> 1) * 32;
    int wn_base = (warp & 1) * 64;

    float acc[2][8][4];
    #pragma unroll
    for (int i = 0; i < 2; i++)
        #pragma unroll
        for (int j = 0; j < 8; j++)
            #pragma unroll
            for (int r = 0; r < 4; r++) acc[i][j][r] = 0.f;

    int ar = tid >> 3, ac = (tid & 7) * 4;     // A loader: 32 rows x 8 float4
    int wr = tid >> 5, wc = (tid & 31) * 4;    // W loader: 8 rows x 32 float4

    // Pre-resolve gathered row pointers for this thread's 4 A rows
    const float* arow_ptr[4];
    #pragma unroll
    for (int rr = 0; rr < 4; rr++) {
        int r = ar + rr * 32;
        int grow = m0 + r;
        if (MODE == 1) {
            int srcrow = gidx[grow];
            arow_ptr[rr] = A + (size_t)srcrow * lda;
        } else {
            arow_ptr[rr] = A + (size_t)grow * lda;
        }
    }

    int nchunks = K / BK;

    auto stage = [&](int bsel, int k0) {
        uint32_t abase = as_u + (uint32_t)bsel * ASZ * 4;
        #pragma unroll
        for (int rr = 0; rr < 4; rr++) {
            int r = ar + rr * 32;
            int gcol = k0 + ac;
            const float* src;
            if (MODE == 3) {
                int grow = m0 + r;
                src = (gcol < DIM) ? (A + (size_t)grow * DIM + gcol)
                                   : (Rp + (size_t)grow * HID + (gcol - DIM));
            } else {
                src = arow_ptr[rr] + gcol;
            }
            cp_async16(abase + (uint32_t)(r * LDAS + ac) * 4, src);
        }
        uint32_t bbase = ws_u + (uint32_t)bsel * WSZ * 4;
        #pragma unroll
        for (int rr = 0; rr < 4; rr++) {
            int r = wr + rr * 8;
            cp_async16(bbase + (uint32_t)(r * LDBS + wc) * 4,
                       W + (size_t)(k0 + r) * N + n0 + wc);
        }
    };

    stage(0, 0);
    CP_COMMIT();

    for (int c = 0; c < nchunks; c++) {
        int cur = c & 1;
        if (c + 1 < nchunks) {
            stage(cur ^ 1, (c + 1) * BK);
            CP_COMMIT();
            CP_WAIT(1);
        } else {
            CP_WAIT(0);
        }
        __syncthreads();

        const float* Ab = As + cur * ASZ;
        const float* Wb = Ws + cur * WSZ;

        #pragma unroll
        for (int kk = 0; kk < 4; kk++) {
            int kb = kk * 8;
            uint32_t afr[2][4], bfr[8][2];
            #pragma unroll
            for (int wm = 0; wm < 2; wm++) {
                int r = wm_base + wm * 16 + (lane >> 2);
                int cidx = kb + (lane & 3);
                afr[wm][0] = __float_as_uint(Ab[r * LDAS + cidx]);
                afr[wm][1] = __float_as_uint(Ab[(r + 8) * LDAS + cidx]);
                afr[wm][2] = __float_as_uint(Ab[r * LDAS + cidx + 4]);
                afr[wm][3] = __float_as_uint(Ab[(r + 8) * LDAS + cidx + 4]);
            }
            #pragma unroll
            for (int wn = 0; wn < 8; wn++) {
                int ccol = wn_base + wn * 8 + (lane >> 2);
                int rrow = kb + (lane & 3);
                bfr[wn][0] = __float_as_uint(Wb[rrow * LDBS + ccol]);
                bfr[wn][1] = __float_as_uint(Wb[(rrow + 4) * LDBS + ccol]);
            }
            #pragma unroll
            for (int wm = 0; wm < 2; wm++)
                #pragma unroll
                for (int wn = 0; wn < 8; wn++)
                    mma8(acc[wm][wn], afr[wm], bfr[wn]);
        }
        __syncthreads();
    }

    // ---- epilogue: + bias, optional relu, optional tf32 round, write ----
    #pragma unroll
    for (int wm = 0; wm < 2; wm++) {
        int r0 = m0 + wm_base + wm * 16 + (lane >> 2);
        #pragma unroll
        for (int wn = 0; wn < 8; wn++) {
            int c0 = n0 + wn_base + wn * 8 + 2 * (lane & 3);
            float b0 = bias[c0], b1v = bias[c0 + 1];
            float v0 = acc[wm][wn][0] + b0;
            float v1 = acc[wm][wn][1] + b1v;
            float v2 = acc[wm][wn][2] + b0;
            float v3 = acc[wm][wn][3] + b1v;
            if (ACT) {
                v0 = fmaxf(v0, 0.f); v1 = fmaxf(v1, 0.f);
                v2 = fmaxf(v2, 0.f); v3 = fmaxf(v3, 0.f);
            }
            if (ROUND) {
                v0 = round_tf32(v0); v1 = round_tf32(v1);
                v2 = round_tf32(v2); v3 = round_tf32(v3);
            }
            float2 p0 = make_float2(v0, v1);
            float2 p1 = make_float2(v2, v3);
            *(float2*)(C + (size_t)r0 * N + c0)       = p0;
            *(float2*)(C + (size_t)(r0 + 8) * N + c0) = p1;
        }
    }
}

// ---------------------------------------------------------------------------
// Weighted reduce (compacted): R[b,:] = sum_g w[b,g] * H3c[g, pos[b,g], :]
// ---------------------------------------------------------------------------
__global__ __launch_bounds__(256)
void reduce_kernel(const float* __restrict__ H3, const float* __restrict__ w,
                   const int* __restrict__ pos, float* __restrict__ R) {
    int idx = blockIdx.x * blockDim.x + threadIdx.x;   // over BATCH * 32 float4s
    int b = idx >> 5;
    int off = idx & 31;
    float4 r = make_float4(0.f, 0.f, 0.f, 0.f);
    const float4* H = (const float4*)H3;
    #pragma unroll
    for (int g = 0; g < NG; g++) {
        float wv = w[(size_t)b * NG + g];
        if (wv != 0.f) {
            int slot = pos[(size_t)b * NG + g];
            float4 h = H[((size_t)g * BATCH + slot) * 32 + off];
            r.x += wv * h.x; r.y += wv * h.y;
            r.z += wv * h.z; r.w += wv * h.w;
        }
    }
    r.x = round_tf32(r.x); r.y = round_tf32(r.y);
    r.z = round_tf32(r.z); r.w = round_tf32(r.w);
    ((float4*)R)[idx] = r;
}

// ---------------------------------------------------------------------------
// Launch
// ---------------------------------------------------------------------------
extern "C" void kernel_launch(void* const* d_in, const int* in_sizes, int n_in,
                              void* d_out, int out_size) {
    (void)in_sizes; (void)n_in; (void)out_size;
    const float* X     = (const float*)d_in[0];
    const float* genre = (const float*)d_in[1];
    const float* W1    = (const float*)d_in[2];
    const float* b1    = (const float*)d_in[3];
    const float* W2    = (const float*)d_in[4];
    const float* b2    = (const float*)d_in[5];
    const float* W3    = (const float*)d_in[6];
    const float* b3    = (const float*)d_in[7];
    const float* Wa    = (const float*)d_in[8];
    const float* ba    = (const float*)d_in[9];
    const float* Wagg  = (const float*)d_in[10];
    const float* bagg  = (const float*)d_in[11];
    float* out = (float*)d_out;

    float *w, *buf1, *H2, *R, *Xr, *W1r, *W2r, *W3r, *Waggr;
    int *counts, *idxArr, *pos;
    cudaGetSymbolAddress((void**)&w,      g_w);
    cudaGetSymbolAddress((void**)&buf1,   g_buf1);
    cudaGetSymbolAddress((void**)&H2,     g_H2);
    cudaGetSymbolAddress((void**)&R,      g_R);
    cudaGetSymbolAddress((void**)&Xr,     g_Xr);
    cudaGetSymbolAddress((void**)&W1r,    g_W1r);
    cudaGetSymbolAddress((void**)&W2r,    g_W2r);
    cudaGetSymbolAddress((void**)&W3r,    g_W3r);
    cudaGetSymbolAddress((void**)&Waggr,  g_Waggr);
    cudaGetSymbolAddress((void**)&counts, g_counts);
    cudaGetSymbolAddress((void**)&idxArr, g_idx);
    cudaGetSymbolAddress((void**)&pos,    g_pos);

    // Unconditional (idempotent, host-side, not captured) — no static guards.
    cudaFuncSetAttribute(gemm_tf32_kernel<1, 1, 1>,
                         cudaFuncAttributeMaxDynamicSharedMemorySize, GEMM_SMEM_BYTES);
    cudaFuncSetAttribute(gemm_tf32_kernel<1, 1, 2>,
                         cudaFuncAttributeMaxDynamicSharedMemorySize, GEMM_SMEM_BYTES);
    cudaFuncSetAttribute(gemm_tf32_kernel<0, 0, 2>,
                         cudaFuncAttributeMaxDynamicSharedMemorySize, GEMM_SMEM_BYTES);
    cudaFuncSetAttribute(gemm_tf32_kernel<1, 0, 3>,
                         cudaFuncAttributeMaxDynamicSharedMemorySize, GEMM_SMEM_BYTES);

    // 0) prep: tf32-round all GEMM operands; build membership compaction
    round_kernel<<<512, 256>>>(X,    Xr,    BATCH * DIM / 4);
    round_kernel<<<512, 256>>>(W1,   W1r,   NG * DIM * HID2 / 4);
    round_kernel<<<256, 256>>>(W2,   W2r,   NG * HID2 * HID / 4);
    round_kernel<<<128, 256>>>(W3,   W3r,   NG * HID * HID / 4);
    round_kernel<<<128, 256>>>(Wagg, Waggr, DAGG * DIM / 4);
    zero_kernel<<<288, 256>>>(counts, idxArr);
    compact_kernel<<<NG * BATCH / 256, 256>>>(genre, counts, idxArr, pos);

    // 1) attention weights (masked)
    attn_kernel<<<BATCH / 64, 256>>>(X, genre, Wa, ba, w);

    // 2) H1c = relu(gather(Xr) @ W1r[g] + b1[g])  [compacted rows]
    gemm_tf32_kernel<1, 1, 1><<<dim3(BATCH / BM, HID2 / BN, NG), 256, GEMM_SMEM_BYTES>>>(
        Xr, nullptr, W1r, b1, buf1,
        BATCH, HID2, DIM, DIM,
        0LL, (long long)DIM * HID2, HID2, (long long)BATCH * HID2,
        idxArr, counts);

    // 3) H2c = relu(H1c @ W2r[g] + b2[g])
    gemm_tf32_kernel<1, 1, 2><<<dim3(BATCH / BM, 1, NG), 256, GEMM_SMEM_BYTES>>>(
        buf1, nullptr, W2r, b2, H2,
        BATCH, HID, HID2, HID2,
        (long long)BATCH * HID2, (long long)HID2 * HID, HID, (long long)BATCH * HID,
        idxArr, counts);

    // 4) H3c = H2c @ W3r[g] + b3[g]   (reuse buf1)
    gemm_tf32_kernel<0, 0, 2><<<dim3(BATCH / BM, 1, NG), 256, GEMM_SMEM_BYTES>>>(
        H2, nullptr, W3r, b3, buf1,
        BATCH, HID, HID, HID,
        (long long)BATCH * HID, (long long)HID * HID, HID, (long long)BATCH * HID,
        idxArr, counts);

    // 5) R = sum_g w .* H3c[pos]
    reduce_kernel<<<(BATCH * 32) / 256, 256>>>(buf1, w, pos, R);

    // 6) out = relu([Xr, R] @ Waggr + bagg)
    gemm_tf32_kernel<1, 0, 3><<<dim3(BATCH / BM, DIM / BN, 1), 256, GEMM_SMEM_BYTES>>>(
        Xr, R, Waggr, bagg, out,
        BATCH, DIM, DAGG, DAGG,
        0LL, 0LL, 0LL, 0LL,
        idxArr, counts);
}